// round 15
// baseline (speedup 1.0000x reference)
#include <cuda_runtime.h>
#include <cuda_fp16.h>
#include <cstdint>

// FeatureTransformer_5909875000395
//   d_in[0]: ft_ics  int32  [16384, 32]   (pad = -1)
//   d_in[1]: weight  fp32   [41024, 257]
//   d_in[2]: bias    fp32   [256]
// Output: fts [16384,256] then psqt [16384,1]  (fp32)
//
// bias_full = [0, bias[0..255]]: fts col 0 no bias, col c gets bias[c-1],
// psqt col gets bias[255].
//
// R15: gather frozen at the LTS wall (19.8us, ~13 TB/s of L2 reads).
// Convert: same proven lane-pair access pattern, now 4 rows per warp
// (32 loads in flight per thread) to close the tail-latency gap to its
// ~5us byte floor.

#define BATCH      16384
#define MAX_ACTIVE 32
#define N_OUT      256
#define N_IN       41024
#define ROW_W      257

// +1 zero row at index N_IN for padded slots (device globals zero-init;
// convert_kernel never writes row N_IN, so it stays zero across replays).
__device__ __half g_wh[(size_t)(N_IN + 1) * N_OUT];   // ~21 MB, 512B rows
__device__ float  g_ps[N_IN + 1];                      // psqt col, fp32

// --------------------------------------------------------------- convert ---
// One warp per 4 weight rows. Per row: lane handles col pairs {p*64+2*lane},
// packed half2 conversion, 4B stores (exact R10/R12/R14 access pattern —
// 2 lines per scalar LDG, 128B coalesced store wavefronts). Full unroll
// batches 32 scalar loads per thread.
__global__ __launch_bounds__(256)
void convert_kernel(const float* __restrict__ w)
{
    const int wg   = (blockIdx.x << 3) + (threadIdx.x >> 5);   // global warp
    const int lane = threadIdx.x & 31;
    const int r0   = wg << 2;                                   // 4 rows/warp

    #pragma unroll
    for (int r = 0; r < 4; ++r) {
        const float* src = w + (size_t)(r0 + r) * ROW_W;
        __half*      dst = g_wh + ((size_t)(r0 + r) << 8);
        #pragma unroll
        for (int p = 0; p < 4; ++p) {
            const int c = (p << 6) + (lane << 1);
            const float a = __ldg(src + c);
            const float b = __ldg(src + c + 1);
            *(__half2*)(dst + c) = __floats2half2_rn(a, b);
        }
    }
    if (lane < 4)
        g_ps[r0 + lane] = __ldg(w + (size_t)(r0 + lane) * ROW_W + 256);
}

// ---------------------------------------------------------------- gather ---
// (frozen at the L2-byte wall — R12/R14, 19.7-19.8us)
// CTA = 256 threads = 4 batch rows x 64 threads. Thread owns cols
// {4*lt .. 4*lt+3} via one uint2 (2x half2) load per index. 32 indices in
// 8 groups of 4, each summed with a 2-level fp16 tree then fp32. psqt loads
// issued early so they complete under the main loop.
__global__ __launch_bounds__(256, 6)
void gather_kernel(const int*   __restrict__ ft_ics,
                   const float* __restrict__ bias,
                   float*       __restrict__ out)
{
    __shared__ int sidx[4 * MAX_ACTIVE];

    const int tid  = threadIdx.x;
    const int row0 = blockIdx.x * 4;

    if (tid < 4 * MAX_ACTIVE) {
        int v = ft_ics[row0 * MAX_ACTIVE + tid];
        sidx[tid] = (v < 0) ? N_IN : v;              // branchless in the loop
    }
    __syncthreads();

    const int g    = tid >> 6;          // row group: 0..3
    const int lt   = tid & 63;          // thread within row
    const int row  = row0 + g;
    const int c    = lt << 2;           // first col owned (multiple of 4)
    const int* idxp = &sidx[g * MAX_ACTIVE];

    // psqt load issued early; butterfly-reduced after the main loop.
    const int wid  = tid >> 5;
    const int lane = tid & 31;
    float p = (wid < 4) ? __ldg(g_ps + sidx[wid * MAX_ACTIVE + lane]) : 0.0f;

    // Shifted-bias init: col c gets bias[c-1] (col 0 gets 0).
    float a0 = (c == 0) ? 0.0f : __ldg(bias + c - 1);
    float a1 = __ldg(bias + c);
    float a2 = __ldg(bias + c + 1);
    float a3 = __ldg(bias + c + 2);

    #pragma unroll
    for (int i = 0; i < MAX_ACTIVE; i += 4) {
        const int i0 = idxp[i];
        const int i1 = idxp[i + 1];
        const int i2 = idxp[i + 2];
        const int i3 = idxp[i + 3];
        const uint2 v0 = __ldg((const uint2*)(g_wh + ((size_t)i0 << 8)) + lt);
        const uint2 v1 = __ldg((const uint2*)(g_wh + ((size_t)i1 << 8)) + lt);
        const uint2 v2 = __ldg((const uint2*)(g_wh + ((size_t)i2 << 8)) + lt);
        const uint2 v3 = __ldg((const uint2*)(g_wh + ((size_t)i3 << 8)) + lt);

        // 2-level fp16 tree on each half2 lane pair.
        const __half2 sx = __hadd2(
            __hadd2(*(const __half2*)&v0.x, *(const __half2*)&v1.x),
            __hadd2(*(const __half2*)&v2.x, *(const __half2*)&v3.x));
        const __half2 sy = __hadd2(
            __hadd2(*(const __half2*)&v0.y, *(const __half2*)&v1.y),
            __hadd2(*(const __half2*)&v2.y, *(const __half2*)&v3.y));

        const float2 fx = __half22float2(sx);
        const float2 fy = __half22float2(sy);
        a0 += fx.x; a1 += fx.y; a2 += fy.x; a3 += fy.y;
    }

    *(float4*)(out + (size_t)row * N_OUT + c) = make_float4(a0, a1, a2, a3);

    // psqt: warps 0..3 handle rows 0..3 (g_ps[N_IN] == 0 for pads).
    if (wid < 4) {
        #pragma unroll
        for (int off = 16; off > 0; off >>= 1)
            p += __shfl_xor_sync(0xffffffffu, p, off);
        if (lane == 0)
            out[(size_t)BATCH * N_OUT + row0 + wid] = p + __ldg(bias + 255);
    }
}

// ---------------------------------------------------------------- launch ---
extern "C" void kernel_launch(void* const* d_in, const int* in_sizes, int n_in,
                              void* d_out, int out_size)
{
    const int*   ft_ics = (const int*)  d_in[0];
    const float* weight = (const float*)d_in[1];
    const float* bias   = (const float*)d_in[2];
    float*       out    = (float*)      d_out;

    convert_kernel<<<N_IN / 32, 256>>>(weight);
    gather_kernel<<<BATCH / 4, 256>>>(ft_ics, bias, out);
}

// round 16
// speedup vs baseline: 1.0012x; 1.0012x over previous
#include <cuda_runtime.h>
#include <cuda_fp16.h>
#include <cstdint>

// FeatureTransformer_5909875000395 — FINAL (R14 configuration, best: 26.3us)
//   d_in[0]: ft_ics  int32  [16384, 32]   (pad = -1)
//   d_in[1]: weight  fp32   [41024, 257]
//   d_in[2]: bias    fp32   [256]
// Output: fts [16384,256] then psqt [16384,1]  (fp32)
//
// bias_full = [0, bias[0..255]]: fts col 0 no bias, col c gets bias[c-1],
// psqt col gets bias[255].
//
// Design (converged over 15 rounds):
//  - weight table converted to fp16 once per launch (fp32 kept for psqt col):
//    halves the gather bytes; storage rounding gives rel_err 3.75e-4 < 1e-3.
//  - gather: 64 threads/row, uint2 (4 cols) per thread, 8 groups of 4 indices
//    with 2-level fp16 add tree then fp32 accumulate; branchless padding via
//    an all-zero row at index N_IN; psqt loads hoisted above the main loop.
//    Measured at the LTS structural cap (~13 TB/s L2 reads, 19.7-19.9us).
//  - convert: 2 rows/warp, lane-pair loads (2 lines/LDG — optimal for the
//    4B-aligned 257-float stride), packed half2 4B stores.

#define BATCH      16384
#define MAX_ACTIVE 32
#define N_OUT      256
#define N_IN       41024
#define ROW_W      257

// +1 zero row at index N_IN for padded slots (device globals zero-init;
// convert_kernel never writes row N_IN, so it stays zero across replays).
__device__ __half g_wh[(size_t)(N_IN + 1) * N_OUT];   // ~21 MB, 512B rows
__device__ float  g_ps[N_IN + 1];                      // psqt col, fp32

// --------------------------------------------------------------- convert ---
// One warp per 2 weight rows. Per row: lane handles col pairs {p*64+2*lane},
// packed half2 conversion, 4B stores.
__global__ __launch_bounds__(256)
void convert_kernel(const float* __restrict__ w)
{
    const int wg   = (blockIdx.x << 3) + (threadIdx.x >> 5);   // global warp
    const int lane = threadIdx.x & 31;
    const int r0   = wg << 1;                                   // 2 rows/warp

    #pragma unroll
    for (int r = 0; r < 2; ++r) {
        const float* src = w + (size_t)(r0 + r) * ROW_W;
        __half*      dst = g_wh + ((size_t)(r0 + r) << 8);
        #pragma unroll
        for (int p = 0; p < 4; ++p) {
            const int c = (p << 6) + (lane << 1);
            const float a = __ldg(src + c);
            const float b = __ldg(src + c + 1);
            *(__half2*)(dst + c) = __floats2half2_rn(a, b);
        }
    }
    if (lane < 2)
        g_ps[r0 + lane] = __ldg(w + (size_t)(r0 + lane) * ROW_W + 256);
}

// ---------------------------------------------------------------- gather ---
// CTA = 256 threads = 4 batch rows x 64 threads. Thread owns cols
// {4*lt .. 4*lt+3} via one uint2 (2x half2) load per index. 32 indices in
// 8 groups of 4, each summed with a 2-level fp16 tree then fp32. psqt loads
// issued early so they complete under the main loop.
__global__ __launch_bounds__(256, 6)
void gather_kernel(const int*   __restrict__ ft_ics,
                   const float* __restrict__ bias,
                   float*       __restrict__ out)
{
    __shared__ int sidx[4 * MAX_ACTIVE];

    const int tid  = threadIdx.x;
    const int row0 = blockIdx.x * 4;

    if (tid < 4 * MAX_ACTIVE) {
        int v = ft_ics[row0 * MAX_ACTIVE + tid];
        sidx[tid] = (v < 0) ? N_IN : v;              // branchless in the loop
    }
    __syncthreads();

    const int g    = tid >> 6;          // row group: 0..3
    const int lt   = tid & 63;          // thread within row
    const int row  = row0 + g;
    const int c    = lt << 2;           // first col owned (multiple of 4)
    const int* idxp = &sidx[g * MAX_ACTIVE];

    // psqt load issued early; butterfly-reduced after the main loop.
    const int wid  = tid >> 5;
    const int lane = tid & 31;
    float p = (wid < 4) ? __ldg(g_ps + sidx[wid * MAX_ACTIVE + lane]) : 0.0f;

    // Shifted-bias init: col c gets bias[c-1] (col 0 gets 0).
    float a0 = (c == 0) ? 0.0f : __ldg(bias + c - 1);
    float a1 = __ldg(bias + c);
    float a2 = __ldg(bias + c + 1);
    float a3 = __ldg(bias + c + 2);

    #pragma unroll
    for (int i = 0; i < MAX_ACTIVE; i += 4) {
        const int i0 = idxp[i];
        const int i1 = idxp[i + 1];
        const int i2 = idxp[i + 2];
        const int i3 = idxp[i + 3];
        const uint2 v0 = __ldg((const uint2*)(g_wh + ((size_t)i0 << 8)) + lt);
        const uint2 v1 = __ldg((const uint2*)(g_wh + ((size_t)i1 << 8)) + lt);
        const uint2 v2 = __ldg((const uint2*)(g_wh + ((size_t)i2 << 8)) + lt);
        const uint2 v3 = __ldg((const uint2*)(g_wh + ((size_t)i3 << 8)) + lt);

        // 2-level fp16 tree on each half2 lane pair.
        const __half2 sx = __hadd2(
            __hadd2(*(const __half2*)&v0.x, *(const __half2*)&v1.x),
            __hadd2(*(const __half2*)&v2.x, *(const __half2*)&v3.x));
        const __half2 sy = __hadd2(
            __hadd2(*(const __half2*)&v0.y, *(const __half2*)&v1.y),
            __hadd2(*(const __half2*)&v2.y, *(const __half2*)&v3.y));

        const float2 fx = __half22float2(sx);
        const float2 fy = __half22float2(sy);
        a0 += fx.x; a1 += fx.y; a2 += fy.x; a3 += fy.y;
    }

    *(float4*)(out + (size_t)row * N_OUT + c) = make_float4(a0, a1, a2, a3);

    // psqt: warps 0..3 handle rows 0..3 (g_ps[N_IN] == 0 for pads).
    if (wid < 4) {
        #pragma unroll
        for (int off = 16; off > 0; off >>= 1)
            p += __shfl_xor_sync(0xffffffffu, p, off);
        if (lane == 0)
            out[(size_t)BATCH * N_OUT + row0 + wid] = p + __ldg(bias + 255);
    }
}

// ---------------------------------------------------------------- launch ---
extern "C" void kernel_launch(void* const* d_in, const int* in_sizes, int n_in,
                              void* d_out, int out_size)
{
    const int*   ft_ics = (const int*)  d_in[0];
    const float* weight = (const float*)d_in[1];
    const float* bias   = (const float*)d_in[2];
    float*       out    = (float*)      d_out;

    convert_kernel<<<N_IN / 16, 256>>>(weight);
    gather_kernel<<<BATCH / 4, 256>>>(ft_ics, bias, out);
}

// round 17
// speedup vs baseline: 1.0094x; 1.0083x over previous
#include <cuda_runtime.h>
#include <cuda_fp16.h>
#include <cstdint>

// FeatureTransformer_5909875000395 — FINAL (converged, best observed: 26.3us)
//   d_in[0]: ft_ics  int32  [16384, 32]   (pad = -1)
//   d_in[1]: weight  fp32   [41024, 257]
//   d_in[2]: bias    fp32   [256]
// Output: fts [16384,256] then psqt [16384,1]  (fp32)
//
// bias_full = [0, bias[0..255]]: fts col 0 no bias, col c gets bias[c-1],
// psqt col gets bias[255].
//
// Converged design (17 rounds):
//  - fp16 weight table built once per launch (psqt col kept fp32): halves
//    gather bytes; rel_err 3.75e-4 << 1e-3.
//  - gather: 4 rows x 64 thr per CTA, uint2 (4 cols)/thread, 8 groups of 4
//    indices with a 2-level fp16 add tree then fp32 accumulate; branchless
//    padding via an all-zero row at index N_IN; psqt loads hoisted above the
//    main loop. Runs at the LTS structural cap (~13 TB/s L2 reads).
//  - convert: 2 rows/warp, lane-pair loads, packed half2 4B stores — the
//    empirical optimum for the 4B-aligned 257-float source stride.

#define BATCH      16384
#define MAX_ACTIVE 32
#define N_OUT      256
#define N_IN       41024
#define ROW_W      257

// +1 zero row at index N_IN for padded slots (device globals zero-init;
// convert_kernel never writes row N_IN, so it stays zero across replays).
__device__ __half g_wh[(size_t)(N_IN + 1) * N_OUT];   // ~21 MB, 512B rows
__device__ float  g_ps[N_IN + 1];                      // psqt col, fp32

// --------------------------------------------------------------- convert ---
__global__ __launch_bounds__(256)
void convert_kernel(const float* __restrict__ w)
{
    const int wg   = (blockIdx.x << 3) + (threadIdx.x >> 5);   // global warp
    const int lane = threadIdx.x & 31;
    const int r0   = wg << 1;                                   // 2 rows/warp

    #pragma unroll
    for (int r = 0; r < 2; ++r) {
        const float* src = w + (size_t)(r0 + r) * ROW_W;
        __half*      dst = g_wh + ((size_t)(r0 + r) << 8);
        #pragma unroll
        for (int p = 0; p < 4; ++p) {
            const int c = (p << 6) + (lane << 1);
            const float a = __ldg(src + c);
            const float b = __ldg(src + c + 1);
            *(__half2*)(dst + c) = __floats2half2_rn(a, b);
        }
    }
    if (lane < 2)
        g_ps[r0 + lane] = __ldg(w + (size_t)(r0 + lane) * ROW_W + 256);
}

// ---------------------------------------------------------------- gather ---
__global__ __launch_bounds__(256, 6)
void gather_kernel(const int*   __restrict__ ft_ics,
                   const float* __restrict__ bias,
                   float*       __restrict__ out)
{
    __shared__ int sidx[4 * MAX_ACTIVE];

    const int tid  = threadIdx.x;
    const int row0 = blockIdx.x * 4;

    if (tid < 4 * MAX_ACTIVE) {
        int v = ft_ics[row0 * MAX_ACTIVE + tid];
        sidx[tid] = (v < 0) ? N_IN : v;              // branchless in the loop
    }
    __syncthreads();

    const int g    = tid >> 6;          // row group: 0..3
    const int lt   = tid & 63;          // thread within row
    const int row  = row0 + g;
    const int c    = lt << 2;           // first col owned (multiple of 4)
    const int* idxp = &sidx[g * MAX_ACTIVE];

    // psqt load issued early; butterfly-reduced after the main loop.
    const int wid  = tid >> 5;
    const int lane = tid & 31;
    float p = (wid < 4) ? __ldg(g_ps + sidx[wid * MAX_ACTIVE + lane]) : 0.0f;

    // Shifted-bias init: col c gets bias[c-1] (col 0 gets 0).
    float a0 = (c == 0) ? 0.0f : __ldg(bias + c - 1);
    float a1 = __ldg(bias + c);
    float a2 = __ldg(bias + c + 1);
    float a3 = __ldg(bias + c + 2);

    #pragma unroll
    for (int i = 0; i < MAX_ACTIVE; i += 4) {
        const int i0 = idxp[i];
        const int i1 = idxp[i + 1];
        const int i2 = idxp[i + 2];
        const int i3 = idxp[i + 3];
        const uint2 v0 = __ldg((const uint2*)(g_wh + ((size_t)i0 << 8)) + lt);
        const uint2 v1 = __ldg((const uint2*)(g_wh + ((size_t)i1 << 8)) + lt);
        const uint2 v2 = __ldg((const uint2*)(g_wh + ((size_t)i2 << 8)) + lt);
        const uint2 v3 = __ldg((const uint2*)(g_wh + ((size_t)i3 << 8)) + lt);

        // 2-level fp16 tree on each half2 lane pair.
        const __half2 sx = __hadd2(
            __hadd2(*(const __half2*)&v0.x, *(const __half2*)&v1.x),
            __hadd2(*(const __half2*)&v2.x, *(const __half2*)&v3.x));
        const __half2 sy = __hadd2(
            __hadd2(*(const __half2*)&v0.y, *(const __half2*)&v1.y),
            __hadd2(*(const __half2*)&v2.y, *(const __half2*)&v3.y));

        const float2 fx = __half22float2(sx);
        const float2 fy = __half22float2(sy);
        a0 += fx.x; a1 += fx.y; a2 += fy.x; a3 += fy.y;
    }

    *(float4*)(out + (size_t)row * N_OUT + c) = make_float4(a0, a1, a2, a3);

    // psqt: warps 0..3 handle rows 0..3 (g_ps[N_IN] == 0 for pads).
    if (wid < 4) {
        #pragma unroll
        for (int off = 16; off > 0; off >>= 1)
            p += __shfl_xor_sync(0xffffffffu, p, off);
        if (lane == 0)
            out[(size_t)BATCH * N_OUT + row0 + wid] = p + __ldg(bias + 255);
    }
}

// ---------------------------------------------------------------- launch ---
extern "C" void kernel_launch(void* const* d_in, const int* in_sizes, int n_in,
                              void* d_out, int out_size)
{
    const int*   ft_ics = (const int*)  d_in[0];
    const float* weight = (const float*)d_in[1];
    const float* bias   = (const float*)d_in[2];
    float*       out    = (float*)      d_out;

    convert_kernel<<<N_IN / 16, 256>>>(weight);
    gather_kernel<<<BATCH / 4, 256>>>(ft_ics, bias, out);
}